// round 13
// baseline (speedup 1.0000x reference)
#include <cuda_runtime.h>
#include <cuda_fp16.h>
#include <cstdint>
#include <math.h>

// Problem constants (fixed)
#define OUT_FEATURES 11008
#define IN_FEATURES  4096
#define TOKENS       64
#define BLOCK_SIZE   1024
#define NUM_BLOCKS   (OUT_FEATURES * IN_FEATURES / BLOCK_SIZE)   // 44032
#define W_ELEMS      (OUT_FEATURES * IN_FEATURES)                // 45,088,768
#define KSPLIT       8

// Scratch (device globals; no allocation allowed)
__device__ __half g_W[W_ELEMS];
__device__ __half g_x[TOKENS * IN_FEATURES];
__device__ int    g_qflag;                      // 0=int8, 1=int32, 2=float32
__device__ int    g_ostart[NUM_BLOCKS + 1];     // outlier lower_bound per 1024-block
__device__ float  g_part[KSPLIT][TOKENS * OUT_FEATURES];

// ---------------------------------------------------------------------------
// Kernel 0: detect storage layout of int8_data (harness may upcast).
// ---------------------------------------------------------------------------
__global__ void detect_kernel(const void* __restrict__ qdata)
{
    __shared__ int c_i32, c_f32;
    if (threadIdx.x == 0) { c_i32 = 0; c_f32 = 0; }
    __syncthreads();
    const int t = threadIdx.x;   // 64 threads
    int w = ((const int*)qdata)[t];
    bool vi32 = (w >= -127 && w <= 127);
    float f = __int_as_float(w);
    bool vf32 = (!vi32) && isfinite(f) && fabsf(f) <= 127.0f && f == truncf(f);
    if (vi32) atomicAdd(&c_i32, 1);
    if (vf32) atomicAdd(&c_f32, 1);
    __syncthreads();
    if (t == 0) {
        int flag = 0;
        if (c_i32 >= 32) flag = 1;
        else if (c_f32 >= 32) flag = 2;
        g_qflag = flag;
    }
}

// ---------------------------------------------------------------------------
// Kernel 1: convert x (float32, fp16-exact) -> fp16 scratch.
// ---------------------------------------------------------------------------
__global__ void __launch_bounds__(256) convert_x_kernel(const float* __restrict__ x)
{
    const int i = blockIdx.x * blockDim.x + threadIdx.x;
    float4 f = ((const float4*)x)[i];
    __half2 h0 = __floats2half2_rn(f.x, f.y);
    __half2 h1 = __floats2half2_rn(f.z, f.w);
    uint2 p;
    p.x = *(unsigned*)&h0;
    p.y = *(unsigned*)&h1;
    ((uint2*)g_x)[i] = p;
}

// ---------------------------------------------------------------------------
// Kernel 2: invert fp16_pos -> per-block outlier lower bounds.
// ---------------------------------------------------------------------------
__global__ void __launch_bounds__(256) ostart_kernel(
    const int* __restrict__ fp16_pos, int n_fp16)
{
    const int stride = gridDim.x * blockDim.x;
    for (int i = blockIdx.x * blockDim.x + threadIdx.x; i <= n_fp16; i += stride) {
        int lo = (i == 0) ? 0 : ((fp16_pos[i - 1] >> 10) + 1);
        int hi = (i == n_fp16) ? NUM_BLOCKS : (fp16_pos[i] >> 10);
        for (int b = lo; b <= hi; b++) g_ostart[b] = i;
    }
}

// ---------------------------------------------------------------------------
// Kernel 3: dense dequant (rank-and-copy). One CTA per 1024-elem block.
// Output-centric: thread t owns positions 8t..8t+7, ONE uint4 store.
// k(p) = p - #{outliers < p}; value = q[cb + k] * scale. Outlier positions
// get garbage here and are fixed by patch_kernel afterward.
// Input window staged coalesced into smem (uniform unguarded fast path).
// ---------------------------------------------------------------------------
__global__ void __launch_bounds__(128) dequant_kernel(
    const void*  __restrict__ qdata,
    const float* __restrict__ scales,
    const int*   __restrict__ fp16_pos,
    int n_q)
{
    __shared__ __align__(16) float s_q[1040];  // input window (words or bytes)
    __shared__ int s_o[1024];                  // local outlier positions

    const int b    = blockIdx.x;
    const int t    = threadIdx.x;
    const int base = b << 10;

    const int o_s  = g_ostart[b];
    const int o_e  = g_ostart[b + 1];
    const int cnt  = o_e - o_s;
    const int cb   = base - o_s;           // compact index of block's first int8
    const int flag = g_qflag;
    const float sc = scales[b];

    for (int i = t; i < cnt; i += 128)
        s_o[i] = fp16_pos[o_s + i] - base;

    int head;
    if (flag == 0) {
        const int a0 = cb & ~15;
        head = cb - a0;                    // 0..15 (bytes)
        const int8_t* q = (const int8_t*)qdata;
        int8_t* sb = (int8_t*)s_q;
        if (t < 65) {                      // 65 x 16B = 1040 B >= head + 1024
            const int off = t * 16;
            if (a0 + off + 16 <= n_q) {
                *(int4*)(sb + off) = *(const int4*)(q + a0 + off);
            } else {
                #pragma unroll
                for (int j = 0; j < 16; j++)
                    sb[off + j] = (a0 + off + j < n_q) ? q[a0 + off + j] : (int8_t)0;
            }
        }
    } else {
        const int a0 = cb & ~3;
        head = cb - a0;                    // 0..3 (words)
        const float* qf = (const float*)qdata;
        if (a0 + 1028 <= n_q) {            // uniform fast path (interior CTAs)
            const float4* q4 = (const float4*)(qf + a0);
            *(float4*)(s_q + t * 4)         = q4[t];
            *(float4*)(s_q + (t + 128) * 4) = q4[t + 128];
            if (t == 0) *(float4*)(s_q + 256 * 4) = q4[256];
        } else {
            for (int idx = t; idx < 257; idx += 128) {
                #pragma unroll
                for (int j = 0; j < 4; j++) {
                    const int gi = a0 + idx * 4 + j;
                    s_q[idx * 4 + j] = (gi < n_q) ? qf[gi] : 0.0f;
                }
            }
        }
    }
    __syncthreads();

    const int p0 = t * 8;                  // first output position of this thread

    // rank r[s] = #{outliers < p0+s}; independent compares, skipped if cnt==0
    int r[8];
    #pragma unroll
    for (int s = 0; s < 8; s++) r[s] = 0;
    for (int j = 0; j < cnt; j++) {
        const int o = s_o[j];
        #pragma unroll
        for (int s = 0; s < 8; s++) r[s] += (o < p0 + s) ? 1 : 0;
    }

    // gather from smem, scale, pack 8 halves -> one uint4 store
    unsigned h[4];
    if (flag == 2) {
        #pragma unroll
        for (int s = 0; s < 8; s += 2) {
            float v0 = s_q[head + p0 + s     - r[s]]     * sc;
            float v1 = s_q[head + p0 + s + 1 - r[s + 1]] * sc;
            __half2 hh = __floats2half2_rn(v0, v1);
            h[s >> 1] = *(unsigned*)&hh;
        }
    } else if (flag == 1) {
        const int* si = (const int*)s_q;
        #pragma unroll
        for (int s = 0; s < 8; s += 2) {
            float v0 = (float)si[head + p0 + s     - r[s]]     * sc;
            float v1 = (float)si[head + p0 + s + 1 - r[s + 1]] * sc;
            __half2 hh = __floats2half2_rn(v0, v1);
            h[s >> 1] = *(unsigned*)&hh;
        }
    } else {
        const int8_t* sb = (const int8_t*)s_q;
        #pragma unroll
        for (int s = 0; s < 8; s += 2) {
            float v0 = (float)sb[head + p0 + s     - r[s]]     * sc;
            float v1 = (float)sb[head + p0 + s + 1 - r[s + 1]] * sc;
            __half2 hh = __floats2half2_rn(v0, v1);
            h[s >> 1] = *(unsigned*)&hh;
        }
    }

    uint4 pack;
    pack.x = h[0]; pack.y = h[1]; pack.z = h[2]; pack.w = h[3];
    ((uint4*)(g_W + base))[t] = pack;
}

// ---------------------------------------------------------------------------
// Kernel 3b: patch outlier values (exact), after dense pass.
// ---------------------------------------------------------------------------
__global__ void __launch_bounds__(256) patch_kernel(
    const int*   __restrict__ fp16_pos,
    const float* __restrict__ fp16_data,
    int n_fp16)
{
    const int i = blockIdx.x * blockDim.x + threadIdx.x;
    if (i < n_fp16)
        g_W[fp16_pos[i]] = __float2half_rn(fp16_data[i]);
}

// ---------------------------------------------------------------------------
// Kernel 4: split-K GEMM (proven). grid (172, KSPLIT). 64M x 64N,
// K range 512, chunks of 64, 3-stage cp.async, mma.sync m16n8k16.
// ---------------------------------------------------------------------------
#define KC      64
#define KPS     (IN_FEATURES / KSPLIT)   // 512 per split
#define NKC     (KPS / KC)               // 8 chunks
#define STAGES  3
#define SSTRIDE 72
#define STAGE_HALVES (64 * SSTRIDE)      // 4608

__device__ __forceinline__ void cp_async16(void* smem_ptr, const void* gmem_ptr) {
    unsigned saddr = (unsigned)__cvta_generic_to_shared(smem_ptr);
    asm volatile("cp.async.cg.shared.global [%0], [%1], 16;\n" :: "r"(saddr), "l"(gmem_ptr));
}
__device__ __forceinline__ void cp_commit() {
    asm volatile("cp.async.commit_group;\n");
}
template <int N>
__device__ __forceinline__ void cp_wait() {
    asm volatile("cp.async.wait_group %0;\n" :: "n"(N));
}

__global__ void __launch_bounds__(128) gemm_kernel()
{
    extern __shared__ __half smem[];
    __half* As = smem;
    __half* Bs = smem + STAGES * STAGE_HALVES;

    const int n0    = blockIdx.x * 64;
    const int kbase = blockIdx.y * KPS;
    const int t     = threadIdx.x;
    const int warp  = t >> 5;
    const int lane  = t & 31;
    const int g     = lane >> 2;
    const int tid4  = lane & 3;

    const __half* X = g_x;
    const __half* W = g_W;

    auto load_stage = [&](int kc, int st) {
        const int k0 = kbase + kc * KC;
        __half* A = As + st * STAGE_HALVES;
        __half* B = Bs + st * STAGE_HALVES;
        #pragma unroll
        for (int q = 0; q < 4; q++) {
            const int idx = t + q * 128;
            const int row = idx >> 3;
            const int seg = idx & 7;
            cp_async16(A + row * SSTRIDE + seg * 8,
                       X + row * IN_FEATURES + k0 + seg * 8);
            cp_async16(B + row * SSTRIDE + seg * 8,
                       W + (long)(n0 + row) * IN_FEATURES + k0 + seg * 8);
        }
        cp_commit();
    };

    float acc[8][4];
    #pragma unroll
    for (int n = 0; n < 8; n++)
        #pragma unroll
        for (int i = 0; i < 4; i++) acc[n][i] = 0.0f;

    load_stage(0, 0);
    load_stage(1, 1);

    for (int kc = 0; kc < NKC; kc++) {
        const int st = kc % STAGES;
        if (kc == NKC - 1) cp_wait<0>(); else cp_wait<1>();
        __syncthreads();

        if (kc + 2 < NKC) load_stage(kc + 2, (kc + 2) % STAGES);

        const __half* A = As + st * STAGE_HALVES;
        const __half* B = Bs + st * STAGE_HALVES;

        #pragma unroll
        for (int ks = 0; ks < 4; ks++) {
            const int kb = ks * 16;
            unsigned a0, a1, a2, a3;
            {
                const __half* p0 = A + (warp * 16 + g) * SSTRIDE + kb + tid4 * 2;
                const __half* p8 = A + (warp * 16 + g + 8) * SSTRIDE + kb + tid4 * 2;
                a0 = *(const unsigned*)p0;
                a2 = *(const unsigned*)(p0 + 8);
                a1 = *(const unsigned*)p8;
                a3 = *(const unsigned*)(p8 + 8);
            }
            #pragma unroll
            for (int n = 0; n < 8; n++) {
                const __half* pb = B + (n * 8 + g) * SSTRIDE + kb + tid4 * 2;
                unsigned b0 = *(const unsigned*)pb;
                unsigned b1 = *(const unsigned*)(pb + 8);
                asm volatile(
                    "mma.sync.aligned.m16n8k16.row.col.f32.f16.f16.f32 "
                    "{%0,%1,%2,%3}, {%4,%5,%6,%7}, {%8,%9}, {%0,%1,%2,%3};\n"
                    : "+f"(acc[n][0]), "+f"(acc[n][1]), "+f"(acc[n][2]), "+f"(acc[n][3])
                    : "r"(a0), "r"(a1), "r"(a2), "r"(a3), "r"(b0), "r"(b1));
            }
        }
        __syncthreads();
    }

    float* part = g_part[blockIdx.y];
    #pragma unroll
    for (int n = 0; n < 8; n++) {
        const int col = n0 + n * 8 + tid4 * 2;
        const int row0 = warp * 16 + g;
        const int row1 = row0 + 8;
        float2 o0 = make_float2(acc[n][0], acc[n][1]);
        float2 o1 = make_float2(acc[n][2], acc[n][3]);
        *(float2*)(part + row0 * OUT_FEATURES + col) = o0;
        *(float2*)(part + row1 * OUT_FEATURES + col) = o1;
    }
}

// ---------------------------------------------------------------------------
// Kernel 5: reduce split-K partials + bias (fp16-rounding mimic of reference).
// ---------------------------------------------------------------------------
__global__ void __launch_bounds__(256) reduce_kernel(
    const float* __restrict__ bias, float* __restrict__ out)
{
    const int i4 = blockIdx.x * blockDim.x + threadIdx.x;
    const int e0 = i4 * 4;
    const int col = e0 % OUT_FEATURES;

    float4 s = *(const float4*)&g_part[0][e0];
    #pragma unroll
    for (int z = 1; z < KSPLIT; z++) {
        float4 p = *(const float4*)&g_part[z][e0];
        s.x += p.x; s.y += p.y; s.z += p.z; s.w += p.w;
    }

    float4 bf = *(const float4*)(bias + col);

    float4 o;
    o.x = __half2float(__hadd(__float2half_rn(s.x), __float2half_rn(bf.x)));
    o.y = __half2float(__hadd(__float2half_rn(s.y), __float2half_rn(bf.y)));
    o.z = __half2float(__hadd(__float2half_rn(s.z), __float2half_rn(bf.z)));
    o.w = __half2float(__hadd(__float2half_rn(s.w), __float2half_rn(bf.w)));
    *(float4*)(out + e0) = o;
}

// ---------------------------------------------------------------------------
// Launch. Inputs: x, int8_data, fp16_data, scales, bias, int8_pos, fp16_pos,
// block_idx. int8_pos/block_idx unused by design.
// ---------------------------------------------------------------------------
extern "C" void kernel_launch(void* const* d_in, const int* in_sizes, int n_in,
                              void* d_out, int out_size)
{
    const float* x         = (const float*)d_in[0];
    const void*  int8_data = d_in[1];
    const float* fp16_data = (const float*)d_in[2];
    const float* scales    = (const float*)d_in[3];
    const float* bias      = (const float*)d_in[4];
    const int*   fp16_pos  = (const int*)d_in[6];
    const int    n_fp16    = in_sizes[2];
    const int    n_q       = in_sizes[1];   // element count

    detect_kernel<<<1, 64>>>(int8_data);
    convert_x_kernel<<<TOKENS * IN_FEATURES / (256 * 4), 256>>>(x);
    ostart_kernel<<<256, 256>>>(fp16_pos, n_fp16);
    dequant_kernel<<<NUM_BLOCKS, 128>>>(int8_data, scales, fp16_pos, n_q);
    patch_kernel<<<(n_fp16 + 255) / 256, 256>>>(fp16_pos, fp16_data, n_fp16);

    const int smem_bytes = 2 * STAGES * STAGE_HALVES * (int)sizeof(__half); // 55296
    static bool attr_set = false;
    if (!attr_set) {
        cudaFuncSetAttribute(gemm_kernel,
                             cudaFuncAttributeMaxDynamicSharedMemorySize, smem_bytes);
        attr_set = true;
    }
    gemm_kernel<<<dim3(OUT_FEATURES / 64, KSPLIT), 128, smem_bytes>>>();

    reduce_kernel<<<TOKENS * OUT_FEATURES / (256 * 4), 256>>>(bias, (float*)d_out);
}

// round 15
// speedup vs baseline: 1.1021x; 1.1021x over previous
#include <cuda_runtime.h>
#include <cuda_fp16.h>
#include <cstdint>
#include <math.h>

// Problem constants (fixed)
#define OUT_FEATURES 11008
#define IN_FEATURES  4096
#define TOKENS       64
#define BLOCK_SIZE   1024
#define NUM_BLOCKS   (OUT_FEATURES * IN_FEATURES / BLOCK_SIZE)   // 44032
#define W_ELEMS      (OUT_FEATURES * IN_FEATURES)                // 45,088,768
#define KSPLIT       8

// Scratch (device globals; no allocation allowed)
__device__ __half g_W[W_ELEMS];
__device__ __half g_x[TOKENS * IN_FEATURES];
__device__ int    g_qflag;                      // 0=int8, 1=int32, 2=float32
__device__ int    g_ostart[NUM_BLOCKS + 1];     // outlier lower_bound per 1024-block
__device__ float  g_part[KSPLIT][TOKENS * OUT_FEATURES];

// swizzled smem word index: word i -> (i&7)*132 + (i>>3)
#define SWZ(i) ((((i) & 7) * 132) + ((i) >> 3))

// ---------------------------------------------------------------------------
// Kernel 0: detect storage layout of int8_data (harness may upcast).
// ---------------------------------------------------------------------------
__global__ void detect_kernel(const void* __restrict__ qdata)
{
    __shared__ int c_i32, c_f32;
    if (threadIdx.x == 0) { c_i32 = 0; c_f32 = 0; }
    __syncthreads();
    const int t = threadIdx.x;   // 64 threads
    int w = ((const int*)qdata)[t];
    bool vi32 = (w >= -127 && w <= 127);
    float f = __int_as_float(w);
    bool vf32 = (!vi32) && isfinite(f) && fabsf(f) <= 127.0f && f == truncf(f);
    if (vi32) atomicAdd(&c_i32, 1);
    if (vf32) atomicAdd(&c_f32, 1);
    __syncthreads();
    if (t == 0) {
        int flag = 0;
        if (c_i32 >= 32) flag = 1;
        else if (c_f32 >= 32) flag = 2;
        g_qflag = flag;
    }
}

// ---------------------------------------------------------------------------
// Kernel 1: convert x (float32, fp16-exact) -> fp16 scratch.
// ---------------------------------------------------------------------------
__global__ void __launch_bounds__(256) convert_x_kernel(const float* __restrict__ x)
{
    const int i = blockIdx.x * blockDim.x + threadIdx.x;
    float4 f = ((const float4*)x)[i];
    __half2 h0 = __floats2half2_rn(f.x, f.y);
    __half2 h1 = __floats2half2_rn(f.z, f.w);
    uint2 p;
    p.x = *(unsigned*)&h0;
    p.y = *(unsigned*)&h1;
    ((uint2*)g_x)[i] = p;
}

// ---------------------------------------------------------------------------
// Kernel 2: invert fp16_pos -> per-block outlier lower bounds.
// ---------------------------------------------------------------------------
__global__ void __launch_bounds__(256) ostart_kernel(
    const int* __restrict__ fp16_pos, int n_fp16)
{
    const int stride = gridDim.x * blockDim.x;
    for (int i = blockIdx.x * blockDim.x + threadIdx.x; i <= n_fp16; i += stride) {
        int lo = (i == 0) ? 0 : ((fp16_pos[i - 1] >> 10) + 1);
        int hi = (i == n_fp16) ? NUM_BLOCKS : (fp16_pos[i] >> 10);
        for (int b = lo; b <= hi; b++) g_ostart[b] = i;
    }
}

// ---------------------------------------------------------------------------
// Kernel 3: dense dequant (rank-and-copy), conflict-free smem.
// Output-centric: thread t owns positions 8t..8t+7, ONE uint4 store.
// k(p) = p - #{outliers < p}; value = q[cb + k] * scale; outlier positions
// get garbage and are fixed by patch_kernel.
// 4-byte input staged into SWIZZLED smem: gather stride-8 reads become
// bank-conflict-free (word i at (i&7)*132 + (i>>3); pad 132 ≡ 4 mod 32 also
// makes the staging writes conflict-free).
// ---------------------------------------------------------------------------
__global__ void __launch_bounds__(128) dequant_kernel(
    const void*  __restrict__ qdata,
    const float* __restrict__ scales,
    const int*   __restrict__ fp16_pos,
    int n_q)
{
    __shared__ __align__(16) float s_q[1056];  // swizzled window (4B path) / bytes (int8 path)
    __shared__ int s_o[1024];                  // local outlier positions

    const int b    = blockIdx.x;
    const int t    = threadIdx.x;
    const int base = b << 10;

    const int o_s  = g_ostart[b];
    const int o_e  = g_ostart[b + 1];
    const int cnt  = o_e - o_s;
    const int cb   = base - o_s;           // compact index of block's first value
    const int flag = g_qflag;
    const float sc = scales[b];

    for (int i = t; i < cnt; i += 128)
        s_o[i] = fp16_pos[o_s + i] - base;

    int head;
    if (flag == 0) {
        // int8 path: linear byte layout (correctness only; unused in practice)
        const int a0 = cb & ~15;
        head = cb - a0;
        const int8_t* q = (const int8_t*)qdata;
        int8_t* sb = (int8_t*)s_q;
        if (t < 65) {
            const int off = t * 16;
            if (a0 + off + 16 <= n_q) {
                *(int4*)(sb + off) = *(const int4*)(q + a0 + off);
            } else {
                #pragma unroll
                for (int j = 0; j < 16; j++)
                    sb[off + j] = (a0 + off + j < n_q) ? q[a0 + off + j] : (int8_t)0;
            }
        }
    } else {
        const int a0 = cb & ~3;
        head = cb - a0;                    // 0..3 (words)
        const float* qf = (const float*)qdata;
        if (a0 + 1028 <= n_q) {            // uniform fast path (interior CTAs)
            float4 va = *(const float4*)(qf + a0 + 4 * t);
            float4 vb = *(const float4*)(qf + a0 + 512 + 4 * t);
            const int iA = 4 * t;
            const int iB = 512 + 4 * t;
            s_q[SWZ(iA    )] = va.x;  s_q[SWZ(iA + 1)] = va.y;
            s_q[SWZ(iA + 2)] = va.z;  s_q[SWZ(iA + 3)] = va.w;
            s_q[SWZ(iB    )] = vb.x;  s_q[SWZ(iB + 1)] = vb.y;
            s_q[SWZ(iB + 2)] = vb.z;  s_q[SWZ(iB + 3)] = vb.w;
            if (t == 0) {
                float4 vc = *(const float4*)(qf + a0 + 1024);
                s_q[SWZ(1024)] = vc.x;  s_q[SWZ(1025)] = vc.y;
                s_q[SWZ(1026)] = vc.z;  s_q[SWZ(1027)] = vc.w;
            }
        } else {                           // guarded scalar path (tail CTAs)
            for (int idx = t; idx < 1028; idx += 128) {
                const int gi = a0 + idx;
                s_q[SWZ(idx)] = (gi < n_q) ? qf[gi] : 0.0f;
            }
        }
    }
    __syncthreads();

    const int p0 = t * 8;                  // first output position of this thread

    // rank r[s] = #{outliers < p0+s}; independent compares
    int r[8];
    #pragma unroll
    for (int s = 0; s < 8; s++) r[s] = 0;
    for (int j = 0; j < cnt; j++) {
        const int o = s_o[j];
        #pragma unroll
        for (int s = 0; s < 8; s++) r[s] += (o < p0 + s) ? 1 : 0;
    }

    // gather (conflict-free), scale, pack 8 halves -> one uint4 store
    const int bi = head + p0;
    unsigned h[4];
    if (flag == 2) {
        #pragma unroll
        for (int s = 0; s < 8; s += 2) {
            const int i0 = bi + s     - r[s];
            const int i1 = bi + s + 1 - r[s + 1];
            float v0 = s_q[SWZ(i0)] * sc;
            float v1 = s_q[SWZ(i1)] * sc;
            __half2 hh = __floats2half2_rn(v0, v1);
            h[s >> 1] = *(unsigned*)&hh;
        }
    } else if (flag == 1) {
        #pragma unroll
        for (int s = 0; s < 8; s += 2) {
            const int i0 = bi + s     - r[s];
            const int i1 = bi + s + 1 - r[s + 1];
            float v0 = (float)__float_as_int(s_q[SWZ(i0)]) * sc;
            float v1 = (float)__float_as_int(s_q[SWZ(i1)]) * sc;
            __half2 hh = __floats2half2_rn(v0, v1);
            h[s >> 1] = *(unsigned*)&hh;
        }
    } else {
        const int8_t* sb = (const int8_t*)s_q;
        #pragma unroll
        for (int s = 0; s < 8; s += 2) {
            float v0 = (float)sb[bi + s     - r[s]]     * sc;
            float v1 = (float)sb[bi + s + 1 - r[s + 1]] * sc;
            __half2 hh = __floats2half2_rn(v0, v1);
            h[s >> 1] = *(unsigned*)&hh;
        }
    }

    uint4 pack;
    pack.x = h[0]; pack.y = h[1]; pack.z = h[2]; pack.w = h[3];
    ((uint4*)(g_W + base))[t] = pack;
}

// ---------------------------------------------------------------------------
// Kernel 3b: patch outlier values (exact), after dense pass.
// ---------------------------------------------------------------------------
__global__ void __launch_bounds__(256) patch_kernel(
    const int*   __restrict__ fp16_pos,
    const float* __restrict__ fp16_data,
    int n_fp16)
{
    const int i = blockIdx.x * blockDim.x + threadIdx.x;
    if (i < n_fp16)
        g_W[fp16_pos[i]] = __float2half_rn(fp16_data[i]);
}

// ---------------------------------------------------------------------------
// Kernel 4: split-K GEMM (proven). grid (172, KSPLIT). 64M x 64N,
// K range 512, chunks of 64, 3-stage cp.async, mma.sync m16n8k16.
// ---------------------------------------------------------------------------
#define KC      64
#define KPS     (IN_FEATURES / KSPLIT)   // 512 per split
#define NKC     (KPS / KC)               // 8 chunks
#define STAGES  3
#define SSTRIDE 72
#define STAGE_HALVES (64 * SSTRIDE)      // 4608

__device__ __forceinline__ void cp_async16(void* smem_ptr, const void* gmem_ptr) {
    unsigned saddr = (unsigned)__cvta_generic_to_shared(smem_ptr);
    asm volatile("cp.async.cg.shared.global [%0], [%1], 16;\n" :: "r"(saddr), "l"(gmem_ptr));
}
__device__ __forceinline__ void cp_commit() {
    asm volatile("cp.async.commit_group;\n");
}
template <int N>
__device__ __forceinline__ void cp_wait() {
    asm volatile("cp.async.wait_group %0;\n" :: "n"(N));
}

__global__ void __launch_bounds__(128) gemm_kernel()
{
    extern __shared__ __half smem[];
    __half* As = smem;
    __half* Bs = smem + STAGES * STAGE_HALVES;

    const int n0    = blockIdx.x * 64;
    const int kbase = blockIdx.y * KPS;
    const int t     = threadIdx.x;
    const int warp  = t >> 5;
    const int lane  = t & 31;
    const int g     = lane >> 2;
    const int tid4  = lane & 3;

    const __half* X = g_x;
    const __half* W = g_W;

    auto load_stage = [&](int kc, int st) {
        const int k0 = kbase + kc * KC;
        __half* A = As + st * STAGE_HALVES;
        __half* B = Bs + st * STAGE_HALVES;
        #pragma unroll
        for (int q = 0; q < 4; q++) {
            const int idx = t + q * 128;
            const int row = idx >> 3;
            const int seg = idx & 7;
            cp_async16(A + row * SSTRIDE + seg * 8,
                       X + row * IN_FEATURES + k0 + seg * 8);
            cp_async16(B + row * SSTRIDE + seg * 8,
                       W + (long)(n0 + row) * IN_FEATURES + k0 + seg * 8);
        }
        cp_commit();
    };

    float acc[8][4];
    #pragma unroll
    for (int n = 0; n < 8; n++)
        #pragma unroll
        for (int i = 0; i < 4; i++) acc[n][i] = 0.0f;

    load_stage(0, 0);
    load_stage(1, 1);

    for (int kc = 0; kc < NKC; kc++) {
        const int st = kc % STAGES;
        if (kc == NKC - 1) cp_wait<0>(); else cp_wait<1>();
        __syncthreads();

        if (kc + 2 < NKC) load_stage(kc + 2, (kc + 2) % STAGES);

        const __half* A = As + st * STAGE_HALVES;
        const __half* B = Bs + st * STAGE_HALVES;

        #pragma unroll
        for (int ks = 0; ks < 4; ks++) {
            const int kb = ks * 16;
            unsigned a0, a1, a2, a3;
            {
                const __half* p0 = A + (warp * 16 + g) * SSTRIDE + kb + tid4 * 2;
                const __half* p8 = A + (warp * 16 + g + 8) * SSTRIDE + kb + tid4 * 2;
                a0 = *(const unsigned*)p0;
                a2 = *(const unsigned*)(p0 + 8);
                a1 = *(const unsigned*)p8;
                a3 = *(const unsigned*)(p8 + 8);
            }
            #pragma unroll
            for (int n = 0; n < 8; n++) {
                const __half* pb = B + (n * 8 + g) * SSTRIDE + kb + tid4 * 2;
                unsigned b0 = *(const unsigned*)pb;
                unsigned b1 = *(const unsigned*)(pb + 8);
                asm volatile(
                    "mma.sync.aligned.m16n8k16.row.col.f32.f16.f16.f32 "
                    "{%0,%1,%2,%3}, {%4,%5,%6,%7}, {%8,%9}, {%0,%1,%2,%3};\n"
                    : "+f"(acc[n][0]), "+f"(acc[n][1]), "+f"(acc[n][2]), "+f"(acc[n][3])
                    : "r"(a0), "r"(a1), "r"(a2), "r"(a3), "r"(b0), "r"(b1));
            }
        }
        __syncthreads();
    }

    float* part = g_part[blockIdx.y];
    #pragma unroll
    for (int n = 0; n < 8; n++) {
        const int col = n0 + n * 8 + tid4 * 2;
        const int row0 = warp * 16 + g;
        const int row1 = row0 + 8;
        float2 o0 = make_float2(acc[n][0], acc[n][1]);
        float2 o1 = make_float2(acc[n][2], acc[n][3]);
        *(float2*)(part + row0 * OUT_FEATURES + col) = o0;
        *(float2*)(part + row1 * OUT_FEATURES + col) = o1;
    }
}

// ---------------------------------------------------------------------------
// Kernel 5: reduce split-K partials + bias (fp16-rounding mimic of reference).
// ---------------------------------------------------------------------------
__global__ void __launch_bounds__(256) reduce_kernel(
    const float* __restrict__ bias, float* __restrict__ out)
{
    const int i4 = blockIdx.x * blockDim.x + threadIdx.x;
    const int e0 = i4 * 4;
    const int col = e0 % OUT_FEATURES;

    float4 s = *(const float4*)&g_part[0][e0];
    #pragma unroll
    for (int z = 1; z < KSPLIT; z++) {
        float4 p = *(const float4*)&g_part[z][e0];
        s.x += p.x; s.y += p.y; s.z += p.z; s.w += p.w;
    }

    float4 bf = *(const float4*)(bias + col);

    float4 o;
    o.x = __half2float(__hadd(__float2half_rn(s.x), __float2half_rn(bf.x)));
    o.y = __half2float(__hadd(__float2half_rn(s.y), __float2half_rn(bf.y)));
    o.z = __half2float(__hadd(__float2half_rn(s.z), __float2half_rn(bf.z)));
    o.w = __half2float(__hadd(__float2half_rn(s.w), __float2half_rn(bf.w)));
    *(float4*)(out + e0) = o;
}

// ---------------------------------------------------------------------------
// Launch. Inputs: x, int8_data, fp16_data, scales, bias, int8_pos, fp16_pos,
// block_idx. int8_pos/block_idx unused by design.
// ---------------------------------------------------------------------------
extern "C" void kernel_launch(void* const* d_in, const int* in_sizes, int n_in,
                              void* d_out, int out_size)
{
    const float* x         = (const float*)d_in[0];
    const void*  int8_data = d_in[1];
    const float* fp16_data = (const float*)d_in[2];
    const float* scales    = (const float*)d_in[3];
    const float* bias      = (const float*)d_in[4];
    const int*   fp16_pos  = (const int*)d_in[6];
    const int    n_fp16    = in_sizes[2];
    const int    n_q       = in_sizes[1];   // element count

    detect_kernel<<<1, 64>>>(int8_data);
    convert_x_kernel<<<TOKENS * IN_FEATURES / (256 * 4), 256>>>(x);
    ostart_kernel<<<256, 256>>>(fp16_pos, n_fp16);
    dequant_kernel<<<NUM_BLOCKS, 128>>>(int8_data, scales, fp16_pos, n_q);
    patch_kernel<<<(n_fp16 + 255) / 256, 256>>>(fp16_pos, fp16_data, n_fp16);

    const int smem_bytes = 2 * STAGES * STAGE_HALVES * (int)sizeof(__half); // 55296
    static bool attr_set = false;
    if (!attr_set) {
        cudaFuncSetAttribute(gemm_kernel,
                             cudaFuncAttributeMaxDynamicSharedMemorySize, smem_bytes);
        attr_set = true;
    }
    gemm_kernel<<<dim3(OUT_FEATURES / 64, KSPLIT), 128, smem_bytes>>>();

    reduce_kernel<<<TOKENS * OUT_FEATURES / (256 * 4), 256>>>(bias, (float*)d_out);
}